// round 3
// baseline (speedup 1.0000x reference)
#include <cuda_runtime.h>

// Max pool 2x2 stride 2, NCHW (32,128,224,224) fp32 -> (32,128,112,112)
// HBM-bound streaming: 822MB read + 206MB write. Target ~7.5+ TB/s.
//
// R3: persistent grid-stride kernel, exactly one wave (148 SMs x 8 CTAs x 256t).
// Each thread loops over quads, unrolled x2 -> 8 independent float4 loads in
// flight continuously (no per-block load-pipeline ramp-up, no wave transitions).

#define IW  224
#define IH  224
#define OW  112
#define OH  112
#define OW4 28          // float4 quads per output row (112/4)
#define NC  (32 * 128)
#define TOTAL_QUADS (NC * OH * OW4)   // 12,845,056

__device__ __forceinline__ float4 quad_max(const float* __restrict__ in, int p) {
    const int ow4 = p % OW4;
    const int t1  = p / OW4;
    const int oh  = t1 % OH;
    const int nc  = t1 / OH;

    const long long base = (long long)nc * (IH * IW) + (long long)(2 * oh) * IW + 8 * ow4;
    const float4* p0 = reinterpret_cast<const float4*>(in + base);
    const float4* p1 = reinterpret_cast<const float4*>(in + base + IW);

    const float4 a0 = __ldcs(p0);
    const float4 a1 = __ldcs(p0 + 1);
    const float4 b0 = __ldcs(p1);
    const float4 b1 = __ldcs(p1 + 1);

    float4 r;
    r.x = fmaxf(fmaxf(a0.x, a0.y), fmaxf(b0.x, b0.y));
    r.y = fmaxf(fmaxf(a0.z, a0.w), fmaxf(b0.z, b0.w));
    r.z = fmaxf(fmaxf(a1.x, a1.y), fmaxf(b1.x, b1.y));
    r.w = fmaxf(fmaxf(a1.z, a1.w), fmaxf(b1.z, b1.w));
    return r;
}

__global__ __launch_bounds__(256, 8)
void pool2d_kernel(const float* __restrict__ in, float4* __restrict__ out) {
    const int nthreads = gridDim.x * blockDim.x;          // 303,104
    int p = blockIdx.x * blockDim.x + threadIdx.x;

    // unroll-by-2: two independent quad computations in flight
    for (; p + nthreads < TOTAL_QUADS; p += 2 * nthreads) {
        const int p2 = p + nthreads;
        float4 r0 = quad_max(in, p);
        float4 r1 = quad_max(in, p2);
        __stcs(out + p,  r0);
        __stcs(out + p2, r1);
    }
    if (p < TOTAL_QUADS) {
        __stcs(out + p, quad_max(in, p));
    }
}

extern "C" void kernel_launch(void* const* d_in, const int* in_sizes, int n_in,
                              void* d_out, int out_size) {
    const float* x = (const float*)d_in[0];
    float4* out = (float4*)d_out;

    // one wave: 148 SMs * 8 CTAs/SM (occupancy cap from __launch_bounds__)
    const int blocks  = 148 * 8;   // 1184
    const int threads = 256;

    pool2d_kernel<<<blocks, threads>>>(x, out);
}

// round 4
// speedup vs baseline: 1.0881x; 1.0881x over previous
#include <cuda_runtime.h>

// Max pool 2x2 stride 2, NCHW (32,128,224,224) fp32 -> (32,128,112,112)
// HBM-bound streaming: 822MB read + 206MB write.
//
// R4: die-after-work grid (R3 persistent regressed), 2 output quads per thread.
// Quads are strided by blockDim within a block's 512-quad chunk so warp
// accesses stay coalesced. 8 independent float4 loads front-batched (MLP_p1=8).

#define IW  224
#define IH  224
#define OW  112
#define OH  112
#define OW4 28          // float4 quads per output row (112/4)
#define NC  (32 * 128)
#define TOTAL_QUADS (NC * OH * OW4)   // 12,845,056

__device__ __forceinline__ void decode(int p, const float* __restrict__ in,
                                       const float4** p0, const float4** p1) {
    const int ow4 = p % OW4;
    const int t1  = p / OW4;
    const int oh  = t1 % OH;
    const int nc  = t1 / OH;
    const long long base = (long long)nc * (IH * IW) + (long long)(2 * oh) * IW + 8 * ow4;
    *p0 = reinterpret_cast<const float4*>(in + base);
    *p1 = reinterpret_cast<const float4*>(in + base + IW);
}

__global__ __launch_bounds__(256, 6)
void pool2d_kernel(const float* __restrict__ in, float4* __restrict__ out) {
    // each block covers 512 consecutive quads; thread t does quad t and t+256
    const int pA = blockIdx.x * 512 + threadIdx.x;
    const int pB = pA + 256;

    const float4 *a0p, *a1p, *b0p, *b1p;
    decode(pA, in, &a0p, &b0p);
    decode(pB, in, &a1p, &b1p);

    // 8 independent loads, front-batched
    const float4 a0 = __ldcs(a0p);
    const float4 a2 = __ldcs(a0p + 1);
    const float4 b0 = __ldcs(b0p);
    const float4 b2 = __ldcs(b0p + 1);
    const float4 c0 = __ldcs(a1p);
    const float4 c2 = __ldcs(a1p + 1);
    const float4 d0 = __ldcs(b1p);
    const float4 d2 = __ldcs(b1p + 1);

    float4 r0, r1;
    r0.x = fmaxf(fmaxf(a0.x, a0.y), fmaxf(b0.x, b0.y));
    r0.y = fmaxf(fmaxf(a0.z, a0.w), fmaxf(b0.z, b0.w));
    r0.z = fmaxf(fmaxf(a2.x, a2.y), fmaxf(b2.x, b2.y));
    r0.w = fmaxf(fmaxf(a2.z, a2.w), fmaxf(b2.z, b2.w));

    r1.x = fmaxf(fmaxf(c0.x, c0.y), fmaxf(d0.x, d0.y));
    r1.y = fmaxf(fmaxf(c0.z, c0.w), fmaxf(d0.z, d0.w));
    r1.z = fmaxf(fmaxf(c2.x, c2.y), fmaxf(d2.x, d2.y));
    r1.w = fmaxf(fmaxf(c2.z, c2.w), fmaxf(d2.z, d2.w));

    __stcs(out + pA, r0);
    __stcs(out + pB, r1);
}

extern "C" void kernel_launch(void* const* d_in, const int* in_sizes, int n_in,
                              void* d_out, int out_size) {
    const float* x = (const float*)d_in[0];
    float4* out = (float4*)d_out;

    // TOTAL_QUADS = 12,845,056 = 512 * 25088 exactly (no tail)
    const int blocks  = TOTAL_QUADS / 512;   // 25088
    const int threads = 256;

    pool2d_kernel<<<blocks, threads>>>(x, out);
}